// round 4
// baseline (speedup 1.0000x reference)
#include <cuda_runtime.h>
#include <math.h>

#define Bn 4
#define Hh 384
#define Ww 1280
#define HW (Hh * Ww)
#define BHW (Bn * HW)

// ---------------- scratch (no allocation allowed -> device globals) ----------
__device__ float g_guid[(size_t)Bn * 12 * HW];
__device__ float g_x1  [(size_t)Bn * 32 * HW];
__device__ float g_x2  [(size_t)Bn * 64 * HW];
__device__ float g_oa  [(size_t)Bn * 24 * HW];

// ---------------- kernel 1: disparity warp + guidance assembly ---------------
__global__ void warp_guid_k(const float* __restrict__ coarse,
                            const float* __restrict__ normal,
                            const float* __restrict__ left,
                            const float* __restrict__ right,
                            float* __restrict__ guid) {
    int idx = blockIdx.x * blockDim.x + threadIdx.x;
    if (idx >= BHW) return;
    int x = idx % Ww;
    int y = (idx / Ww) % Hh;
    int b = idx / HW;
    size_t pix = (size_t)y * Ww + x;

    float disp = __ldg(coarse + (size_t)b * HW + pix);
    float xs   = (float)x - disp;
    float x0f  = floorf(xs);
    int   x0   = (int)x0f;
    float w1   = xs - x0f;
    float wgt0 = 1.0f - w1;

    float we[3] = {0.f, 0.f, 0.f};
#pragma unroll
    for (int d = 0; d < 2; ++d) {
        int   xi = x0 + d;
        float vv = (xi >= 0 && xi < Ww) ? 1.0f : 0.0f;
        int   xc = min(max(xi, 0), Ww - 1);
        float w  = (d == 0) ? wgt0 : w1;
#pragma unroll
        for (int c = 0; c < 3; ++c)
            we[c] += w * vv * __ldg(right + ((size_t)(b * 3 + c) * Hh + y) * Ww + xc);
    }

    float* gb = guid + (size_t)b * 12 * HW + pix;
#pragma unroll
    for (int c = 0; c < 3; ++c) {
        float nn = __ldg(normal + (size_t)(b * 3 + c) * HW + pix);
        float ll = __ldg(left   + (size_t)(b * 3 + c) * HW + pix);
        float rr = __ldg(right  + (size_t)(b * 3 + c) * HW + pix);
        gb[(size_t)(c)     * HW] = nn;
        gb[(size_t)(3 + c) * HW] = ll;
        gb[(size_t)(6 + c) * HW] = rr;
        gb[(size_t)(9 + c) * HW] = we[c] - ll;
    }
}

// ---------------- generic fused conv3x3 (+ optional BN + ReLU) ---------------
// Tile: 32(x) x 8(y) outputs per CTA, 256 threads, 1 px/thread, OCB out channels
// per CTA in registers. Weights in smem as [cin][ky][kx][oc] -> LDS.128 per 4 oc.
template <int CIN, int COUT, int OCB, bool BN>
__global__ void conv3x3_k(const float* __restrict__ in,
                          const float* __restrict__ wg,
                          const float* __restrict__ bng, const float* __restrict__ bnb,
                          const float* __restrict__ bnm, const float* __restrict__ bnv,
                          float* __restrict__ out) {
    extern __shared__ float smem[];
    float* s_in = smem;               // CIN * 10 * 34
    float* s_w  = smem + CIN * 340;   // CIN * 9 * OCB

    const int tid  = threadIdx.x;
    const int bx   = blockIdx.x, by = blockIdx.y, bz = blockIdx.z;
    constexpr int nOcb = COUT / OCB;
    const int b   = bz / nOcb;
    const int ocb = bz % nOcb;
    const int x0 = bx * 32 - 1;
    const int y0 = by * 8 - 1;

    // cooperative input tile load (zero-padded)
    const float* inb = in + (size_t)b * CIN * HW;
    for (int i = tid; i < CIN * 340; i += 256) {
        int cin = i / 340, rem = i % 340;
        int r = rem / 34, c = rem % 34;
        int gy = y0 + r, gx = x0 + c;
        float v = 0.0f;
        if (gy >= 0 && gy < Hh && gx >= 0 && gx < Ww)
            v = __ldg(inb + (size_t)cin * HW + (size_t)gy * Ww + gx);
        s_in[i] = v;
    }
    // cooperative weight load, re-laid-out to [cin][ky][kx][oc]
    for (int i = tid; i < CIN * 9 * OCB; i += 256) {
        int oc = i % OCB;
        int t  = i / OCB;      // cin*9 + k
        int cin = t / 9, k = t % 9;
        s_w[i] = __ldg(wg + ((size_t)(ocb * OCB + oc) * CIN + cin) * 9 + k);
    }
    __syncthreads();

    const int tx = tid & 31, ty = tid >> 5;
    float acc[OCB];
#pragma unroll
    for (int o = 0; o < OCB; ++o) acc[o] = 0.0f;

    for (int cin = 0; cin < CIN; ++cin) {
        const float* srow = s_in + cin * 340 + ty * 34 + tx;
        const float* wrow = s_w + cin * 9 * OCB;
#pragma unroll
        for (int ky = 0; ky < 3; ++ky) {
            float r0 = srow[ky * 34 + 0];
            float r1 = srow[ky * 34 + 1];
            float r2 = srow[ky * 34 + 2];
#pragma unroll
            for (int kx = 0; kx < 3; ++kx) {
                float rv = (kx == 0) ? r0 : ((kx == 1) ? r1 : r2);
                const float4* w4 = reinterpret_cast<const float4*>(wrow + (ky * 3 + kx) * OCB);
#pragma unroll
                for (int o4 = 0; o4 < OCB / 4; ++o4) {
                    float4 w = w4[o4];
                    acc[o4 * 4 + 0] += rv * w.x;
                    acc[o4 * 4 + 1] += rv * w.y;
                    acc[o4 * 4 + 2] += rv * w.z;
                    acc[o4 * 4 + 3] += rv * w.w;
                }
            }
        }
    }

    const int ox = bx * 32 + tx, oy = by * 8 + ty;
    float* outb = out + (size_t)b * COUT * HW + (size_t)ocb * OCB * HW + (size_t)oy * Ww + ox;
#pragma unroll
    for (int o = 0; o < OCB; ++o) {
        float v = acc[o];
        if (BN) {
            int oc = ocb * OCB + o;
            float s = __ldg(bng + oc) * rsqrtf(__ldg(bnv + oc) + 1e-5f);
            v = v * s + (__ldg(bnb + oc) - __ldg(bnm + oc) * s);
            v = fmaxf(v, 0.0f);
        }
        outb[(size_t)o * HW] = v;
    }
}

// ---------------- bilinear with border-validity masking ----------------------
__device__ __forceinline__ float bilin(const float* __restrict__ img, float ys, float xs) {
    float y0f = floorf(ys), x0f = floorf(xs);
    int y0 = (int)y0f, x0 = (int)x0f;
    float wy1 = ys - y0f, wx1 = xs - x0f;
    float wy0 = 1.0f - wy1, wx0 = 1.0f - wx1;
    float out = 0.0f;
#pragma unroll
    for (int dy = 0; dy < 2; ++dy) {
        int yy = y0 + dy;
        float wy = dy ? wy1 : wy0;
        bool vy = (yy >= 0 && yy < Hh);
        int yc = min(max(yy, 0), Hh - 1);
#pragma unroll
        for (int dx = 0; dx < 2; ++dx) {
            int xx = x0 + dx;
            float wx = dx ? wx1 : wx0;
            float vv = (vy && xx >= 0 && xx < Ww) ? 1.0f : 0.0f;
            int xc = min(max(xx, 0), Ww - 1);
            out += wy * wx * vv * __ldg(img + (size_t)yc * Ww + xc);
        }
    }
    return out;
}

// ---------------- kernel 5: affinity normalization + non-local propagation ---
__global__ void propagate_k(const float* __restrict__ oa,
                            const float* __restrict__ conf,
                            const float* __restrict__ coarse,
                            const float* __restrict__ ascp,
                            float* __restrict__ out) {
    int idx = blockIdx.x * blockDim.x + threadIdx.x;
    if (idx >= BHW) return;
    int x = idx % Ww;
    int y = (idx / Ww) % Hh;
    int b = idx / HW;

    const float asc = __ldg(ascp) + 1e-8f;
    const float* oab   = oa + (size_t)b * 24 * HW + (size_t)y * Ww + x;
    const float* confb = conf + (size_t)b * HW;
    const float* coarb = coarse + (size_t)b * HW;

    // off = concat([o1,o2]).reshape(B,8,2,H,W): offy[n]=oa[2n], offx[n]=oa[2n+1]
    float offy[8], offx[8], aff[8];
#pragma unroll
    for (int n = 0; n < 8; ++n) {
        offy[n] = __ldg(oab + (size_t)(2 * n) * HW);
        offx[n] = __ldg(oab + (size_t)(2 * n + 1) * HW);
        float a = tanhf(__ldg(oab + (size_t)(16 + n) * HW)) / asc;
        float ca = bilin(confb, (float)y + offy[n], (float)x + offx[n]);
        aff[n] = a * ca;
    }
    float s = 1e-4f;
#pragma unroll
    for (int n = 0; n < 8; ++n) s += fabsf(aff[n]);
    s = fmaxf(s, 1.0f);
    float suma = 0.0f;
#pragma unroll
    for (int n = 0; n < 8; ++n) { aff[n] /= s; suma += aff[n]; }
    float aref = 1.0f - suma;

    float inter = 0.0f;
#pragma unroll
    for (int k = 0; k < 9; ++k) {
        float ky = (float)(k / 3) - 1.0f;
        float kx = (float)(k % 3) - 1.0f;
        float oy, ox, a;
        if (k < 4)       { oy = offy[k];     ox = offx[k];     a = aff[k];     }
        else if (k == 4) { oy = 0.0f;        ox = 0.0f;        a = aref;       }
        else             { oy = offy[k - 1]; ox = offx[k - 1]; a = aff[k - 1]; }
        float sv = bilin(coarb, (float)y + ky + oy, (float)x + kx + ox);
        inter += a * sv;
    }
    inter = fmaxf(inter, 0.0f);
    float cd = __ldg(coarb + (size_t)y * Ww + x);
    out[idx] = fmaxf(0.7f * cd + 0.3f * inter, 0.0f);
}

// ---------------- launch ------------------------------------------------------
extern "C" void kernel_launch(void* const* d_in, const int* in_sizes, int n_in,
                              void* d_out, int out_size) {
    const float* coarse  = (const float*)d_in[0];
    const float* normal  = (const float*)d_in[1];
    const float* left    = (const float*)d_in[2];
    const float* right   = (const float*)d_in[3];
    const float* conf    = (const float*)d_in[4];
    const float* conv1_w = (const float*)d_in[5];
    const float* bn1_g   = (const float*)d_in[6];
    const float* bn1_b   = (const float*)d_in[7];
    const float* bn1_m   = (const float*)d_in[8];
    const float* bn1_v   = (const float*)d_in[9];
    const float* conv2_w = (const float*)d_in[10];
    const float* bn2_g   = (const float*)d_in[11];
    const float* bn2_b   = (const float*)d_in[12];
    const float* bn2_m   = (const float*)d_in[13];
    const float* bn2_v   = (const float*)d_in[14];
    const float* conv3_w = (const float*)d_in[15];
    const float* asc     = (const float*)d_in[16];
    float* out = (float*)d_out;

    float *guid, *x1, *x2, *oa;
    cudaGetSymbolAddress((void**)&guid, g_guid);
    cudaGetSymbolAddress((void**)&x1, g_x1);
    cudaGetSymbolAddress((void**)&x2, g_x2);
    cudaGetSymbolAddress((void**)&oa, g_oa);

    // smem sizes: (CIN*340 + CIN*9*OCB) * 4 bytes
    const int smem1 = (12 * 340 + 12 * 9 * 32) * 4;   // 30144
    const int smem2 = (32 * 340 + 32 * 9 * 16) * 4;   // 61952
    const int smem3 = (64 * 340 + 64 * 9 * 8) * 4;    // 105472
    cudaFuncSetAttribute((const void*)conv3x3_k<12, 32, 32, true>,
                         cudaFuncAttributeMaxDynamicSharedMemorySize, smem1);
    cudaFuncSetAttribute((const void*)conv3x3_k<32, 64, 16, true>,
                         cudaFuncAttributeMaxDynamicSharedMemorySize, smem2);
    cudaFuncSetAttribute((const void*)conv3x3_k<64, 24, 8, false>,
                         cudaFuncAttributeMaxDynamicSharedMemorySize, smem3);

    // 1) warp + guidance
    warp_guid_k<<<(BHW + 255) / 256, 256>>>(coarse, normal, left, right, guid);

    // 2) conv1 + bn + relu  (12 -> 32)
    {
        dim3 g(Ww / 32, Hh / 8, Bn * (32 / 32));
        conv3x3_k<12, 32, 32, true><<<g, 256, smem1>>>(guid, conv1_w,
                                                       bn1_g, bn1_b, bn1_m, bn1_v, x1);
    }
    // 3) conv2 + bn + relu  (32 -> 64)
    {
        dim3 g(Ww / 32, Hh / 8, Bn * (64 / 16));
        conv3x3_k<32, 64, 16, true><<<g, 256, smem2>>>(x1, conv2_w,
                                                       bn2_g, bn2_b, bn2_m, bn2_v, x2);
    }
    // 4) conv3  (64 -> 24)
    {
        dim3 g(Ww / 32, Hh / 8, Bn * (24 / 8));
        conv3x3_k<64, 24, 8, false><<<g, 256, smem3>>>(x2, conv3_w,
                                                       nullptr, nullptr, nullptr, nullptr, oa);
    }
    // 5) propagation epilogue
    propagate_k<<<(BHW + 255) / 256, 256>>>(oa, conf, coarse, asc, out);
}

// round 5
// speedup vs baseline: 1.5156x; 1.5156x over previous
#include <cuda_runtime.h>
#include <math.h>

#define Bn 4
#define Hh 384
#define Ww 1280
#define HW (Hh * Ww)
#define BHW (Bn * HW)

typedef unsigned long long u64;

// ---------------- scratch (no allocation allowed -> device globals) ----------
__device__ float g_guid[(size_t)Bn * 12 * HW];
__device__ float g_x1  [(size_t)Bn * 32 * HW];
__device__ float g_x2  [(size_t)Bn * 64 * HW];
__device__ float g_oa  [(size_t)Bn * 24 * HW];

// ---------------- packed f32x2 helpers (sm_103a) ------------------------------
__device__ __forceinline__ void fma2(u64& d, u64 a, u64 b) {
    asm("fma.rn.f32x2 %0, %1, %2, %0;" : "+l"(d) : "l"(a), "l"(b));
}
__device__ __forceinline__ u64 dup2(float v) {
    u64 r; unsigned int u = __float_as_uint(v);
    asm("mov.b64 %0, {%1, %1};" : "=l"(r) : "r"(u));
    return r;
}
__device__ __forceinline__ float2 unpk(u64 v) {
    float2 f;
    asm("mov.b64 {%0, %1}, %2;" : "=f"(f.x), "=f"(f.y) : "l"(v));
    return f;
}

// ---------------- kernel 1: disparity warp + guidance assembly ---------------
__global__ void warp_guid_k(const float* __restrict__ coarse,
                            const float* __restrict__ normal,
                            const float* __restrict__ left,
                            const float* __restrict__ right,
                            float* __restrict__ guid) {
    int idx = blockIdx.x * blockDim.x + threadIdx.x;
    if (idx >= BHW) return;
    int x = idx % Ww;
    int y = (idx / Ww) % Hh;
    int b = idx / HW;
    size_t pix = (size_t)y * Ww + x;

    float disp = __ldg(coarse + (size_t)b * HW + pix);
    float xs   = (float)x - disp;
    float x0f  = floorf(xs);
    int   x0   = (int)x0f;
    float w1   = xs - x0f;
    float wgt0 = 1.0f - w1;

    float we[3] = {0.f, 0.f, 0.f};
#pragma unroll
    for (int d = 0; d < 2; ++d) {
        int   xi = x0 + d;
        float vv = (xi >= 0 && xi < Ww) ? 1.0f : 0.0f;
        int   xc = min(max(xi, 0), Ww - 1);
        float w  = (d == 0) ? wgt0 : w1;
#pragma unroll
        for (int c = 0; c < 3; ++c)
            we[c] += w * vv * __ldg(right + ((size_t)(b * 3 + c) * Hh + y) * Ww + xc);
    }

    float* gb = guid + (size_t)b * 12 * HW + pix;
#pragma unroll
    for (int c = 0; c < 3; ++c) {
        float nn = __ldg(normal + (size_t)(b * 3 + c) * HW + pix);
        float ll = __ldg(left   + (size_t)(b * 3 + c) * HW + pix);
        float rr = __ldg(right  + (size_t)(b * 3 + c) * HW + pix);
        gb[(size_t)(c)     * HW] = nn;
        gb[(size_t)(3 + c) * HW] = ll;
        gb[(size_t)(6 + c) * HW] = rr;
        gb[(size_t)(9 + c) * HW] = we[c] - ll;
    }
}

// ---------------- fused conv3x3 v2: f32x2 packed, 2 px/thread, cin-chunked ---
// CTA tile: 64(x) x 8(y) outputs, 256 threads (tx in [0,32) handles x = 2*tx+{0,1}).
// Weights in smem [cin][ky][kx][oc]; channel pairs consumed as ulonglong2.
// Input tile per cin: 10 rows x 66 cols, loaded in chunks of CC channels.
template <int CIN, int CC, int COUT, int OCB, bool BN>
__global__ void __launch_bounds__(256, 2)
conv3x3_v2(const float* __restrict__ in,
           const float* __restrict__ wg,
           const float* __restrict__ bng, const float* __restrict__ bnb,
           const float* __restrict__ bnm, const float* __restrict__ bnv,
           float* __restrict__ out) {
    extern __shared__ float smem[];
    float* s_w  = smem;                      // CIN * 9 * OCB
    float* s_in = smem + CIN * 9 * OCB;      // CC * 10 * 66

    const int tid = threadIdx.x;
    const int bx = blockIdx.x, by = blockIdx.y, bz = blockIdx.z;
    constexpr int nOcb = COUT / OCB;
    const int b   = bz / nOcb;
    const int ocb = bz % nOcb;
    const int x0 = bx * 64 - 1;
    const int y0 = by * 8 - 1;
    const int tx = tid & 31, ty = tid >> 5;

    // weights once: [cin][ky*3+kx][oc]
    for (int i = tid; i < CIN * 9 * OCB; i += 256) {
        int oc = i % OCB;
        int t  = i / OCB;
        int cin = t / 9, k = t % 9;
        s_w[i] = __ldg(wg + ((size_t)(ocb * OCB + oc) * CIN + cin) * 9 + k);
    }

    u64 acc0[OCB / 2], acc1[OCB / 2];
#pragma unroll
    for (int j = 0; j < OCB / 2; ++j) { acc0[j] = 0ull; acc1[j] = 0ull; }

    const float* inb = in + (size_t)b * CIN * HW;

    for (int c0 = 0; c0 < CIN; c0 += CC) {
        __syncthreads();
        // load input chunk (zero-padded halo)
        for (int i = tid; i < CC * 660; i += 256) {
            int cin = i / 660, rem = i % 660;
            int r = rem / 66, c = rem % 66;
            int gy = y0 + r, gx = x0 + c;
            float v = 0.0f;
            if (gy >= 0 && gy < Hh && gx >= 0 && gx < Ww)
                v = __ldg(inb + (size_t)(c0 + cin) * HW + (size_t)gy * Ww + gx);
            s_in[i] = v;
        }
        __syncthreads();

#pragma unroll 1
        for (int cc = 0; cc < CC; ++cc) {
            const float* srow = s_in + cc * 660 + ty * 66 + 2 * tx;
            const float* wci  = s_w + (size_t)(c0 + cc) * 9 * OCB;
#pragma unroll
            for (int ky = 0; ky < 3; ++ky) {
                float2 a01 = *reinterpret_cast<const float2*>(srow + ky * 66);
                float2 a23 = *reinterpret_cast<const float2*>(srow + ky * 66 + 2);
                u64 d0 = dup2(a01.x), d1 = dup2(a01.y), d2 = dup2(a23.x), d3 = dup2(a23.y);
#pragma unroll
                for (int kx = 0; kx < 3; ++kx) {
                    u64 a0 = (kx == 0) ? d0 : ((kx == 1) ? d1 : d2);
                    u64 a1 = (kx == 0) ? d1 : ((kx == 1) ? d2 : d3);
                    const ulonglong2* wp =
                        reinterpret_cast<const ulonglong2*>(wci + (ky * 3 + kx) * OCB);
#pragma unroll
                    for (int p = 0; p < OCB / 4; ++p) {
                        ulonglong2 w = wp[p];
                        fma2(acc0[p * 2 + 0], a0, w.x);
                        fma2(acc0[p * 2 + 1], a0, w.y);
                        fma2(acc1[p * 2 + 0], a1, w.x);
                        fma2(acc1[p * 2 + 1], a1, w.y);
                    }
                }
            }
        }
    }

    const int oxb = bx * 64 + 2 * tx;
    const int oy  = by * 8 + ty;
    float* outb = out + (size_t)b * COUT * HW + (size_t)ocb * OCB * HW
                      + (size_t)oy * Ww + oxb;
#pragma unroll
    for (int j = 0; j < OCB / 2; ++j) {
        float2 p0 = unpk(acc0[j]);   // (ch 2j, ch 2j+1) at pixel 0
        float2 p1 = unpk(acc1[j]);   // (ch 2j, ch 2j+1) at pixel 1
        float va0 = p0.x, va1 = p1.x;   // channel 2j
        float vb0 = p0.y, vb1 = p1.y;   // channel 2j+1
        if (BN) {
            int oa = ocb * OCB + 2 * j, ob = oa + 1;
            float sa = __ldg(bng + oa) * rsqrtf(__ldg(bnv + oa) + 1e-5f);
            float ta = __ldg(bnb + oa) - __ldg(bnm + oa) * sa;
            float sb = __ldg(bng + ob) * rsqrtf(__ldg(bnv + ob) + 1e-5f);
            float tb = __ldg(bnb + ob) - __ldg(bnm + ob) * sb;
            va0 = fmaxf(va0 * sa + ta, 0.0f);
            va1 = fmaxf(va1 * sa + ta, 0.0f);
            vb0 = fmaxf(vb0 * sb + tb, 0.0f);
            vb1 = fmaxf(vb1 * sb + tb, 0.0f);
        }
        *reinterpret_cast<float2*>(outb + (size_t)(2 * j) * HW)     = make_float2(va0, va1);
        *reinterpret_cast<float2*>(outb + (size_t)(2 * j + 1) * HW) = make_float2(vb0, vb1);
    }
}

// ---------------- bilinear with border-validity masking ----------------------
__device__ __forceinline__ float bilin(const float* __restrict__ img, float ys, float xs) {
    float y0f = floorf(ys), x0f = floorf(xs);
    int y0 = (int)y0f, x0 = (int)x0f;
    float wy1 = ys - y0f, wx1 = xs - x0f;
    float wy0 = 1.0f - wy1, wx0 = 1.0f - wx1;
    float out = 0.0f;
#pragma unroll
    for (int dy = 0; dy < 2; ++dy) {
        int yy = y0 + dy;
        float wy = dy ? wy1 : wy0;
        bool vy = (yy >= 0 && yy < Hh);
        int yc = min(max(yy, 0), Hh - 1);
#pragma unroll
        for (int dx = 0; dx < 2; ++dx) {
            int xx = x0 + dx;
            float wx = dx ? wx1 : wx0;
            float vv = (vy && xx >= 0 && xx < Ww) ? 1.0f : 0.0f;
            int xc = min(max(xx, 0), Ww - 1);
            out += wy * wx * vv * __ldg(img + (size_t)yc * Ww + xc);
        }
    }
    return out;
}

// ---------------- kernel 5: affinity normalization + non-local propagation ---
__global__ void propagate_k(const float* __restrict__ oa,
                            const float* __restrict__ conf,
                            const float* __restrict__ coarse,
                            const float* __restrict__ ascp,
                            float* __restrict__ out) {
    int idx = blockIdx.x * blockDim.x + threadIdx.x;
    if (idx >= BHW) return;
    int x = idx % Ww;
    int y = (idx / Ww) % Hh;
    int b = idx / HW;

    const float asc = __ldg(ascp) + 1e-8f;
    const float* oab   = oa + (size_t)b * 24 * HW + (size_t)y * Ww + x;
    const float* confb = conf + (size_t)b * HW;
    const float* coarb = coarse + (size_t)b * HW;

    float offy[8], offx[8], aff[8];
#pragma unroll
    for (int n = 0; n < 8; ++n) {
        offy[n] = __ldg(oab + (size_t)(2 * n) * HW);
        offx[n] = __ldg(oab + (size_t)(2 * n + 1) * HW);
        float a = tanhf(__ldg(oab + (size_t)(16 + n) * HW)) / asc;
        float ca = bilin(confb, (float)y + offy[n], (float)x + offx[n]);
        aff[n] = a * ca;
    }
    float s = 1e-4f;
#pragma unroll
    for (int n = 0; n < 8; ++n) s += fabsf(aff[n]);
    s = fmaxf(s, 1.0f);
    float suma = 0.0f;
#pragma unroll
    for (int n = 0; n < 8; ++n) { aff[n] /= s; suma += aff[n]; }
    float aref = 1.0f - suma;

    float inter = 0.0f;
#pragma unroll
    for (int k = 0; k < 9; ++k) {
        float ky = (float)(k / 3) - 1.0f;
        float kx = (float)(k % 3) - 1.0f;
        float oy, ox, a;
        if (k < 4)       { oy = offy[k];     ox = offx[k];     a = aff[k];     }
        else if (k == 4) { oy = 0.0f;        ox = 0.0f;        a = aref;       }
        else             { oy = offy[k - 1]; ox = offx[k - 1]; a = aff[k - 1]; }
        float sv = bilin(coarb, (float)y + ky + oy, (float)x + kx + ox);
        inter += a * sv;
    }
    inter = fmaxf(inter, 0.0f);
    float cd = __ldg(coarb + (size_t)y * Ww + x);
    out[idx] = fmaxf(0.7f * cd + 0.3f * inter, 0.0f);
}

// ---------------- launch ------------------------------------------------------
extern "C" void kernel_launch(void* const* d_in, const int* in_sizes, int n_in,
                              void* d_out, int out_size) {
    const float* coarse  = (const float*)d_in[0];
    const float* normal  = (const float*)d_in[1];
    const float* left    = (const float*)d_in[2];
    const float* right   = (const float*)d_in[3];
    const float* conf    = (const float*)d_in[4];
    const float* conv1_w = (const float*)d_in[5];
    const float* bn1_g   = (const float*)d_in[6];
    const float* bn1_b   = (const float*)d_in[7];
    const float* bn1_m   = (const float*)d_in[8];
    const float* bn1_v   = (const float*)d_in[9];
    const float* conv2_w = (const float*)d_in[10];
    const float* bn2_g   = (const float*)d_in[11];
    const float* bn2_b   = (const float*)d_in[12];
    const float* bn2_m   = (const float*)d_in[13];
    const float* bn2_v   = (const float*)d_in[14];
    const float* conv3_w = (const float*)d_in[15];
    const float* asc     = (const float*)d_in[16];
    float* out = (float*)d_out;

    float *guid, *x1, *x2, *oa;
    cudaGetSymbolAddress((void**)&guid, g_guid);
    cudaGetSymbolAddress((void**)&x1, g_x1);
    cudaGetSymbolAddress((void**)&x2, g_x2);
    cudaGetSymbolAddress((void**)&oa, g_oa);

    // smem: weights CIN*9*OCB + input chunk CC*660 (floats)
    const int smem1 = (12 * 9 * 16 + 12 * 660) * 4;   // 38,592 B
    const int smem2 = (32 * 9 * 16 + 16 * 660) * 4;   // 60,672 B
    const int smem3 = (64 * 9 * 12 + 16 * 660) * 4;   // 69,888 B
    cudaFuncSetAttribute((const void*)conv3x3_v2<12, 12, 32, 16, true>,
                         cudaFuncAttributeMaxDynamicSharedMemorySize, smem1);
    cudaFuncSetAttribute((const void*)conv3x3_v2<32, 16, 64, 16, true>,
                         cudaFuncAttributeMaxDynamicSharedMemorySize, smem2);
    cudaFuncSetAttribute((const void*)conv3x3_v2<64, 16, 24, 12, false>,
                         cudaFuncAttributeMaxDynamicSharedMemorySize, smem3);

    // 1) warp + guidance
    warp_guid_k<<<(BHW + 255) / 256, 256>>>(coarse, normal, left, right, guid);

    // 2) conv1 + bn + relu  (12 -> 32), OCB=16 -> z = 4*2
    {
        dim3 g(Ww / 64, Hh / 8, Bn * (32 / 16));
        conv3x3_v2<12, 12, 32, 16, true><<<g, 256, smem1>>>(guid, conv1_w,
                                                            bn1_g, bn1_b, bn1_m, bn1_v, x1);
    }
    // 3) conv2 + bn + relu  (32 -> 64), OCB=16 -> z = 4*4
    {
        dim3 g(Ww / 64, Hh / 8, Bn * (64 / 16));
        conv3x3_v2<32, 16, 64, 16, true><<<g, 256, smem2>>>(x1, conv2_w,
                                                            bn2_g, bn2_b, bn2_m, bn2_v, x2);
    }
    // 4) conv3  (64 -> 24), OCB=12 -> z = 4*2
    {
        dim3 g(Ww / 64, Hh / 8, Bn * (24 / 12));
        conv3x3_v2<64, 16, 24, 12, false><<<g, 256, smem3>>>(x2, conv3_w,
                                                             nullptr, nullptr, nullptr, nullptr, oa);
    }
    // 5) propagation epilogue
    propagate_k<<<(BHW + 255) / 256, 256>>>(oa, conf, coarse, asc, out);
}

// round 7
// speedup vs baseline: 5.2774x; 3.4821x over previous
#include <cuda_runtime.h>
#include <cuda_fp16.h>
#include <math.h>
#include <stdint.h>

#define Bn 4
#define Hh 384
#define Ww 1280
#define HW (Hh * Ww)
#define BHW (Bn * HW)

typedef unsigned int u32;

// ---------------- scratch (device globals; half2 packed as u32) --------------
__device__ u32   g_guid[(size_t)Bn * 6 * HW];    // 12 ch as 6 half2 planes
__device__ u32   g_x1  [(size_t)Bn * 16 * HW];   // 32 ch as 16 half2 planes
__device__ u32   g_x2  [(size_t)Bn * 32 * HW];   // 64 ch as 32 half2 planes
__device__ float g_oa  [(size_t)Bn * 24 * HW];   // fp32 planar
// pre-packed fp16 GEMM-B weights: [n][9*CINP] as half2 (u32)
__device__ u32   g_w1[32 * 72];    // NM=32, K9=144
__device__ u32   g_w2[64 * 144];   // NM=64, K9=288
__device__ u32   g_w3[32 * 288];   // NM=32, K9=576

// ---------------- PTX helpers -------------------------------------------------
__device__ __forceinline__ u32 smem_u32(const void* p) {
    u32 a;
    asm("{ .reg .u64 t; cvta.to.shared.u64 t, %1; cvt.u32.u64 %0, t; }" : "=r"(a) : "l"(p));
    return a;
}
__device__ __forceinline__ void ldmA(u32* a, u32 addr) {
    asm volatile("ldmatrix.sync.aligned.m8n8.x4.shared.b16 {%0,%1,%2,%3}, [%4];"
        : "=r"(a[0]), "=r"(a[1]), "=r"(a[2]), "=r"(a[3]) : "r"(addr));
}
__device__ __forceinline__ void ldmB(u32* b, u32 addr) {
    asm volatile("ldmatrix.sync.aligned.m8n8.x2.shared.b16 {%0,%1}, [%2];"
        : "=r"(b[0]), "=r"(b[1]) : "r"(addr));
}
__device__ __forceinline__ void mma16816(float* d, const u32* a, const u32* b) {
    asm volatile("mma.sync.aligned.m16n8k16.row.col.f32.f16.f16.f32 "
        "{%0,%1,%2,%3}, {%4,%5,%6,%7}, {%8,%9}, {%0,%1,%2,%3};"
        : "+f"(d[0]), "+f"(d[1]), "+f"(d[2]), "+f"(d[3])
        : "r"(a[0]), "r"(a[1]), "r"(a[2]), "r"(a[3]), "r"(b[0]), "r"(b[1]));
}

// ---------------- weight prep: OIHW fp32 -> [n][9*CINP] fp16 pairs -----------
__device__ __forceinline__ u32 packw(const float* __restrict__ wg,
                                     int n, int j, int CIN, int CINP, int COUT) {
    int k = 2 * j, t = k / CINP, c = k % CINP;
    float v0 = 0.f, v1 = 0.f;
    if (n < COUT) {
        if (c < CIN)     v0 = __ldg(wg + ((size_t)n * CIN + c) * 9 + t);
        if (c + 1 < CIN) v1 = __ldg(wg + ((size_t)n * CIN + c + 1) * 9 + t);
    }
    __half2 h = __floats2half2_rn(v0, v1);
    return *(u32*)&h;
}
__global__ void prep_w(const float* __restrict__ w1,
                       const float* __restrict__ w2,
                       const float* __restrict__ w3) {
    int i = blockIdx.x * 256 + threadIdx.x;
    const int S1 = 32 * 72, S2 = 64 * 144, S3 = 32 * 288;
    if (i < S1) {
        g_w1[i] = packw(w1, i / 72, i % 72, 12, 16, 32);
    } else if (i < S1 + S2) {
        int q = i - S1;
        g_w2[q] = packw(w2, q / 144, q % 144, 32, 32, 64);
    } else if (i < S1 + S2 + S3) {
        int q = i - S1 - S2;
        g_w3[q] = packw(w3, q / 288, q % 288, 64, 64, 24);
    }
}

// ---------------- kernel 1: disparity warp + guidance (half2 out) ------------
__global__ void warp_guid_k(const float* __restrict__ coarse,
                            const float* __restrict__ normal,
                            const float* __restrict__ left,
                            const float* __restrict__ right,
                            u32* __restrict__ guid) {
    int idx = blockIdx.x * blockDim.x + threadIdx.x;
    if (idx >= BHW) return;
    int x = idx % Ww;
    int y = (idx / Ww) % Hh;
    int b = idx / HW;
    size_t pix = (size_t)y * Ww + x;

    float disp = __ldg(coarse + (size_t)b * HW + pix);
    float xs   = (float)x - disp;
    float x0f  = floorf(xs);
    int   x0   = (int)x0f;
    float w1   = xs - x0f;
    float wgt0 = 1.0f - w1;

    float we[3] = {0.f, 0.f, 0.f};
#pragma unroll
    for (int d = 0; d < 2; ++d) {
        int   xi = x0 + d;
        float vv = (xi >= 0 && xi < Ww) ? 1.0f : 0.0f;
        int   xc = min(max(xi, 0), Ww - 1);
        float w  = (d == 0) ? wgt0 : w1;
#pragma unroll
        for (int c = 0; c < 3; ++c)
            we[c] += w * vv * __ldg(right + ((size_t)(b * 3 + c) * Hh + y) * Ww + xc);
    }

    float v[12];
#pragma unroll
    for (int c = 0; c < 3; ++c) {
        v[c]     = __ldg(normal + (size_t)(b * 3 + c) * HW + pix);
        v[3 + c] = __ldg(left   + (size_t)(b * 3 + c) * HW + pix);
        v[6 + c] = __ldg(right  + (size_t)(b * 3 + c) * HW + pix);
        v[9 + c] = we[c] - v[3 + c];
    }
    u32* gb = guid + (size_t)b * 6 * HW + pix;
#pragma unroll
    for (int p = 0; p < 6; ++p) {
        __half2 h = __floats2half2_rn(v[2 * p], v[2 * p + 1]);
        gb[(size_t)p * HW] = *(u32*)&h;
    }
}

// ---------------- mma.sync implicit-GEMM conv3x3 ------------------------------
// CTA: 128 pixels of one output row (b,y) x NM out channels. 256 thr = 8 warps,
// warp grid 4(M) x 2(N): warp tile 32 x WN.
// A staged once as [3 rows][130 x][CINP+8 ch] fp16 (no 9x im2col duplication);
// tap (ky,kx) A-fragments are ldmatrix at shifted addresses.
// B staged as [NM][9*CINP + 8] fp16 from pre-packed global.
template <int CIN, int CINP, int COUT, int NM, int WN, bool FP16OUT>
__global__ void __launch_bounds__(256)
conv3x3_mma(const u32* __restrict__ in,    // half2 planes [b][CIN/2][H][W]
            const u32* __restrict__ wB,    // packed fp16 pairs [n][K9/2]
            const float* __restrict__ bng, const float* __restrict__ bnb,
            const float* __restrict__ bnm, const float* __restrict__ bnv,
            void* __restrict__ outp) {
    constexpr int K9   = 9 * CINP;
    constexpr int KP   = K9 + 8;       // B row stride (fp16), conflict-free
    constexpr int ASTR = CINP + 8;     // A x-stride (fp16), conflict-free
    constexpr int PP   = CINP / 2;
    constexpr int NI   = WN / 8;

    extern __shared__ char smem[];
    __half* sB = (__half*)smem;                       // NM * KP
    __half* sA = (__half*)(smem + (size_t)NM * KP * 2); // 3*130*ASTR

    const int tid = threadIdx.x;
    const int x0 = blockIdx.x * 128, y = blockIdx.y, b = blockIdx.z;

    // ---- stage B (u32 copy of packed fp16 pairs) ----
    for (int i = tid; i < NM * (K9 / 2); i += 256) {
        int n = i / (K9 / 2), j = i % (K9 / 2);
        *(u32*)(sB + (size_t)n * KP + 2 * j) = __ldg(wB + i);
    }
    // ---- stage A: 3 rows x 130 x CINP fp16 (pad channels / borders zeroed) --
    const u32* inb = in + (size_t)b * (CIN / 2) * HW;
    for (int i = tid; i < 3 * PP * 130; i += 256) {
        int xloc = i % 130;
        int rp   = i / 130;
        int r = rp / PP, p = rp % PP;
        int yy = y + r - 1, xx = x0 - 1 + xloc;
        u32 v = 0;
        if (p < CIN / 2 && yy >= 0 && yy < Hh && (unsigned)xx < (unsigned)Ww)
            v = __ldg(inb + (size_t)p * HW + (size_t)yy * Ww + xx);
        *(u32*)(sA + ((size_t)(r * 130 + xloc)) * ASTR + 2 * p) = v;
    }
    __syncthreads();

    const int lane = tid & 31, wid = tid >> 5;
    const int wm = wid & 3, wn = wid >> 2;
    const int m0 = wm * 32;

    const u32 aBase = smem_u32(sA);
    const u32 bBase = smem_u32(sB);
    const int rowA = lane & 15;
    const int kofA = (lane >> 4) * 8;
    const int rowB = lane & 7;
    const int kofB = ((lane >> 3) & 1) * 8;

    float d[2][NI][4];
#pragma unroll
    for (int mi = 0; mi < 2; ++mi)
#pragma unroll
        for (int ni = 0; ni < NI; ++ni)
#pragma unroll
            for (int c = 0; c < 4; ++c) d[mi][ni][c] = 0.0f;

#pragma unroll
    for (int t = 0; t < 9; ++t) {
        const int ky = t / 3, kx = t % 3;
        u32 aRow0 = aBase + (u32)(((ky * 130 + m0 + rowA + kx) * ASTR + kofA) * 2);
        u32 aRow1 = aRow0 + 16 * ASTR * 2;
        u32 bRow  = bBase + (u32)((((wn * WN + rowB) * KP) + t * CINP + kofB) * 2);
#pragma unroll
        for (int kk = 0; kk < CINP / 16; ++kk) {
            u32 a0[4], a1[4];
            ldmA(a0, aRow0 + kk * 32);
            ldmA(a1, aRow1 + kk * 32);
#pragma unroll
            for (int ni = 0; ni < NI; ++ni) {
                u32 bb[2];
                ldmB(bb, bRow + (u32)(ni * 8 * KP * 2) + kk * 32);
                mma16816(d[0][ni], a0, bb);
                mma16816(d[1][ni], a1, bb);
            }
        }
    }

    // ---- epilogue ----
    const int r4 = lane >> 2, c4 = lane & 3;
#pragma unroll
    for (int ni = 0; ni < NI; ++ni) {
        int ch = wn * WN + ni * 8 + c4 * 2;
        float s0 = 1.f, t0 = 0.f, s1 = 1.f, t1 = 0.f;
        if (FP16OUT) {
            s0 = __ldg(bng + ch)     * rsqrtf(__ldg(bnv + ch) + 1e-5f);
            t0 = __ldg(bnb + ch)     - __ldg(bnm + ch) * s0;
            s1 = __ldg(bng + ch + 1) * rsqrtf(__ldg(bnv + ch + 1) + 1e-5f);
            t1 = __ldg(bnb + ch + 1) - __ldg(bnm + ch + 1) * s1;
        }
#pragma unroll
        for (int mi = 0; mi < 2; ++mi) {
            int x = x0 + m0 + mi * 16 + r4;
            if (FP16OUT) {
                u32* oh = (u32*)outp + (size_t)b * (COUT / 2) * HW
                                     + (size_t)(ch >> 1) * HW + (size_t)y * Ww;
                float v00 = fmaxf(d[mi][ni][0] * s0 + t0, 0.f);
                float v01 = fmaxf(d[mi][ni][1] * s1 + t1, 0.f);
                float v10 = fmaxf(d[mi][ni][2] * s0 + t0, 0.f);
                float v11 = fmaxf(d[mi][ni][3] * s1 + t1, 0.f);
                __half2 h0 = __floats2half2_rn(v00, v01);
                __half2 h1 = __floats2half2_rn(v10, v11);
                oh[x]     = *(u32*)&h0;
                oh[x + 8] = *(u32*)&h1;
            } else if (ch < COUT) {
                float* of = (float*)outp + (size_t)b * COUT * HW + (size_t)y * Ww;
                of[(size_t)ch * HW + x]           = d[mi][ni][0];
                of[(size_t)(ch + 1) * HW + x]     = d[mi][ni][1];
                of[(size_t)ch * HW + x + 8]       = d[mi][ni][2];
                of[(size_t)(ch + 1) * HW + x + 8] = d[mi][ni][3];
            }
        }
    }
}

// ---------------- bilinear with border-validity masking ----------------------
__device__ __forceinline__ float bilin(const float* __restrict__ img, float ys, float xs) {
    float y0f = floorf(ys), x0f = floorf(xs);
    int y0 = (int)y0f, x0 = (int)x0f;
    float wy1 = ys - y0f, wx1 = xs - x0f;
    float wy0 = 1.0f - wy1, wx0 = 1.0f - wx1;
    float out = 0.0f;
#pragma unroll
    for (int dy = 0; dy < 2; ++dy) {
        int yy = y0 + dy;
        float wy = dy ? wy1 : wy0;
        bool vy = (yy >= 0 && yy < Hh);
        int yc = min(max(yy, 0), Hh - 1);
#pragma unroll
        for (int dx = 0; dx < 2; ++dx) {
            int xx = x0 + dx;
            float wx = dx ? wx1 : wx0;
            float vv = (vy && xx >= 0 && xx < Ww) ? 1.0f : 0.0f;
            int xc = min(max(xx, 0), Ww - 1);
            out += wy * wx * vv * __ldg(img + (size_t)yc * Ww + xc);
        }
    }
    return out;
}

// ---------------- kernel 5: affinity normalization + propagation -------------
__global__ void propagate_k(const float* __restrict__ oa,
                            const float* __restrict__ conf,
                            const float* __restrict__ coarse,
                            const float* __restrict__ ascp,
                            float* __restrict__ out) {
    int idx = blockIdx.x * blockDim.x + threadIdx.x;
    if (idx >= BHW) return;
    int x = idx % Ww;
    int y = (idx / Ww) % Hh;
    int b = idx / HW;

    const float asc = __ldg(ascp) + 1e-8f;
    const float* oab   = oa + (size_t)b * 24 * HW + (size_t)y * Ww + x;
    const float* confb = conf + (size_t)b * HW;
    const float* coarb = coarse + (size_t)b * HW;

    float offy[8], offx[8], aff[8];
#pragma unroll
    for (int n = 0; n < 8; ++n) {
        offy[n] = __ldg(oab + (size_t)(2 * n) * HW);
        offx[n] = __ldg(oab + (size_t)(2 * n + 1) * HW);
        float a = tanhf(__ldg(oab + (size_t)(16 + n) * HW)) / asc;
        float ca = bilin(confb, (float)y + offy[n], (float)x + offx[n]);
        aff[n] = a * ca;
    }
    float s = 1e-4f;
#pragma unroll
    for (int n = 0; n < 8; ++n) s += fabsf(aff[n]);
    s = fmaxf(s, 1.0f);
    float suma = 0.0f;
#pragma unroll
    for (int n = 0; n < 8; ++n) { aff[n] /= s; suma += aff[n]; }
    float aref = 1.0f - suma;

    float inter = 0.0f;
#pragma unroll
    for (int k = 0; k < 9; ++k) {
        float ky = (float)(k / 3) - 1.0f;
        float kx = (float)(k % 3) - 1.0f;
        float oy, ox, a;
        if (k < 4)       { oy = offy[k];     ox = offx[k];     a = aff[k];     }
        else if (k == 4) { oy = 0.0f;        ox = 0.0f;        a = aref;       }
        else             { oy = offy[k - 1]; ox = offx[k - 1]; a = aff[k - 1]; }
        float sv = bilin(coarb, (float)y + ky + oy, (float)x + kx + ox);
        inter += a * sv;
    }
    inter = fmaxf(inter, 0.0f);
    float cd = __ldg(coarb + (size_t)y * Ww + x);
    out[idx] = fmaxf(0.7f * cd + 0.3f * inter, 0.0f);
}

// ---------------- launch ------------------------------------------------------
extern "C" void kernel_launch(void* const* d_in, const int* in_sizes, int n_in,
                              void* d_out, int out_size) {
    const float* coarse  = (const float*)d_in[0];
    const float* normal  = (const float*)d_in[1];
    const float* left    = (const float*)d_in[2];
    const float* right   = (const float*)d_in[3];
    const float* conf    = (const float*)d_in[4];
    const float* conv1_w = (const float*)d_in[5];
    const float* bn1_g   = (const float*)d_in[6];
    const float* bn1_b   = (const float*)d_in[7];
    const float* bn1_m   = (const float*)d_in[8];
    const float* bn1_v   = (const float*)d_in[9];
    const float* conv2_w = (const float*)d_in[10];
    const float* bn2_g   = (const float*)d_in[11];
    const float* bn2_b   = (const float*)d_in[12];
    const float* bn2_m   = (const float*)d_in[13];
    const float* bn2_v   = (const float*)d_in[14];
    const float* conv3_w = (const float*)d_in[15];
    const float* asc     = (const float*)d_in[16];
    float* out = (float*)d_out;

    u32 *guid, *x1, *x2, *w1, *w2, *w3;
    float* oa;
    cudaGetSymbolAddress((void**)&guid, g_guid);
    cudaGetSymbolAddress((void**)&x1, g_x1);
    cudaGetSymbolAddress((void**)&x2, g_x2);
    cudaGetSymbolAddress((void**)&oa, g_oa);
    cudaGetSymbolAddress((void**)&w1, g_w1);
    cudaGetSymbolAddress((void**)&w2, g_w2);
    cudaGetSymbolAddress((void**)&w3, g_w3);

    // smem = NM*(K9+8)*2 (B) + 3*130*(CINP+8)*2 (A)
    const int smem1 = 32 * 152 * 2 + 3 * 130 * 24 * 2;   // 28,448
    const int smem2 = 64 * 296 * 2 + 3 * 130 * 40 * 2;   // 69,088
    const int smem3 = 32 * 584 * 2 + 3 * 130 * 72 * 2;   // 93,536
    cudaFuncSetAttribute((const void*)conv3x3_mma<12, 16, 32, 32, 16, true>,
                         cudaFuncAttributeMaxDynamicSharedMemorySize, smem1);
    cudaFuncSetAttribute((const void*)conv3x3_mma<32, 32, 64, 64, 32, true>,
                         cudaFuncAttributeMaxDynamicSharedMemorySize, smem2);
    cudaFuncSetAttribute((const void*)conv3x3_mma<64, 64, 24, 32, 16, false>,
                         cudaFuncAttributeMaxDynamicSharedMemorySize, smem3);

    // 0) weight prep (fp32 OIHW -> packed fp16 GEMM-B)
    prep_w<<<(32 * 72 + 64 * 144 + 32 * 288 + 255) / 256, 256>>>(conv1_w, conv2_w, conv3_w);

    // 1) warp + guidance (half2 out)
    warp_guid_k<<<(BHW + 255) / 256, 256>>>(coarse, normal, left, right, guid);

    dim3 cg(Ww / 128, Hh, Bn);   // (10, 384, 4)

    // 2) conv1 + bn + relu  (12 -> 32)
    conv3x3_mma<12, 16, 32, 32, 16, true><<<cg, 256, smem1>>>(
        guid, w1, bn1_g, bn1_b, bn1_m, bn1_v, x1);

    // 3) conv2 + bn + relu  (32 -> 64)
    conv3x3_mma<32, 32, 64, 64, 32, true><<<cg, 256, smem2>>>(
        x1, w2, bn2_g, bn2_b, bn2_m, bn2_v, x2);

    // 4) conv3 (64 -> 24, N padded to 32)
    conv3x3_mma<64, 64, 24, 32, 16, false><<<cg, 256, smem3>>>(
        x2, w3, nullptr, nullptr, nullptr, nullptr, oa);

    // 5) propagation epilogue
    propagate_k<<<(BHW + 255) / 256, 256>>>(oa, conf, coarse, asc, out);
}